// round 11
// baseline (speedup 1.0000x reference)
#include <cuda_runtime.h>
#include <stdint.h>

#define NN       100000
#define NEMAX    1600000
#define IN_DIM   256
#define HID_DIM  128

typedef unsigned long long u64;

// Scratch (allocation-free rule: __device__ globals, referenced DIRECTLY from
// kernels — no cudaGetSymbolAddress, no symbol-derived kernel arguments).
__device__ int   g_is64;                           // 1 if edge_index is int64
__device__ float g_dinv[NN];                       // rsqrt(weighted degree)
__device__ float g_deg[NN];                        // weighted degree accumulator
__device__ int   g_cnt[NN];                        // incoming-edge histogram
__device__ int   g_rowptr[NN + 1];                 // CSR row pointers (by dst)
__device__ int   g_cursor[NN];                     // fill cursors
__device__ int2  g_edge[NEMAX];                    // CSR: {src, norm-as-bits}
__device__ float g_tmp[(size_t)NN * HID_DIM];      // GEMM output (pre-agg)
__device__ float g_h[(size_t)NN * HID_DIM];        // layer-1 activations

// ---------------------------------------------------------------------------
// f32x2 packed-FMA helpers (SASS FFMA2 — 2 independent fp32 FMAs, 1 instr)
// ---------------------------------------------------------------------------
__device__ __forceinline__ void ffma2(u64& d, u64 a, u64 b) {
    asm("fma.rn.f32x2 %0, %1, %2, %0;" : "+l"(d) : "l"(a), "l"(b));
}
__device__ __forceinline__ u64 dup2(float v) {
    u64 r; asm("mov.b64 %0, {%1, %1};" : "=l"(r) : "f"(v)); return r;
}
__device__ __forceinline__ u64 pack2(float lo, float hi) {
    u64 r; asm("mov.b64 %0, {%1, %2};" : "=l"(r) : "f"(lo), "f"(hi)); return r;
}
__device__ __forceinline__ void unpack2(u64 v, float& lo, float& hi) {
    asm("mov.b64 {%0, %1}, %2;" : "=f"(lo), "=f"(hi) : "l"(v));
}

// ---------------------------------------------------------------------------
// Edge-index dtype detection + safe accessors
// ---------------------------------------------------------------------------
// int64 node indices (< 100000, non-negative) have zero high words. Checking
// 8 odd-position int32 words == 0 identifies int64 vs int32 (P_false ~ 1e-40).
__global__ void k_detect(const int* __restrict__ ei32) {
    int is64 = 1;
    for (int i = 0; i < 8; i++)
        if (ei32[2 * i + 1] != 0) { is64 = 0; break; }
    g_is64 = is64;
}

__device__ __forceinline__ int edge_ld(const void* ei, size_t idx, int is64, int n) {
    int v = is64 ? (int)((const long long*)ei)[idx]
                 : ((const int*)ei)[idx];
    // clamp: any surprise degrades to wrong-but-measurable, not a crash
    return min(max(v, 0), n - 1);
}

// ---------------------------------------------------------------------------
// Normalization + CSR build
// ---------------------------------------------------------------------------
__global__ void k_init(int n) {
    int i = blockIdx.x * blockDim.x + threadIdx.x;
    if (i < n) { g_deg[i] = 1.0f; g_cnt[i] = 0; }   // self-loop weight = 1
}

// One pass over edges: weighted degree (float atomic) + histogram (int atomic)
__global__ void k_edge_pass(const void* __restrict__ ei,
                            const float* __restrict__ w, int E, int n) {
    int e = blockIdx.x * blockDim.x + threadIdx.x;
    if (e < E) {
        int is64 = g_is64;
        int d = edge_ld(ei, (size_t)E + e, is64, n);  // dst row of [2,E]
        atomicAdd(&g_deg[d], w[e]);
        atomicAdd(&g_cnt[d], 1);
    }
}

__global__ void k_dinv(int n) {
    int i = blockIdx.x * blockDim.x + threadIdx.x;
    if (i < n) g_dinv[i] = rsqrtf(g_deg[i]);        // deg >= 1 (self-loop)
}

// Single-block exclusive scan of g_cnt -> g_rowptr AND g_cursor.
__global__ void __launch_bounds__(1024) k_scan(int n) {
    __shared__ int part[1024];
    const int tid = threadIdx.x;
    const int per = (n + 1023) >> 10;
    const int s0 = tid * per;
    const int s1 = min(s0 + per, n);
    int s = 0;
    for (int i = s0; i < s1; i++) s += g_cnt[i];
    part[tid] = s;
    __syncthreads();
    for (int off = 1; off < 1024; off <<= 1) {
        int add = (tid >= off) ? part[tid - off] : 0;
        __syncthreads();
        part[tid] += add;
        __syncthreads();
    }
    int base = (tid == 0) ? 0 : part[tid - 1];
    for (int i = s0; i < s1; i++) {
        g_rowptr[i] = base;
        g_cursor[i] = base;
        base += g_cnt[i];
    }
    if (tid == 1023) g_rowptr[n] = part[1023];
}

// Scatter edges into CSR slots; precompute norm = dinv[src]*w*dinv[dst].
__global__ void k_fill(const void* __restrict__ ei,
                       const float* __restrict__ w, int E, int n) {
    int e = blockIdx.x * blockDim.x + threadIdx.x;
    if (e < E) {
        int is64 = g_is64;
        int s = edge_ld(ei, (size_t)e, is64, n);
        int d = edge_ld(ei, (size_t)E + e, is64, n);
        int pos = atomicAdd(&g_cursor[d], 1);
        float nv = g_dinv[s] * w[e] * g_dinv[d];
        g_edge[pos] = make_int2(s, __float_as_int(nv));
    }
}

// ---------------------------------------------------------------------------
// Tiled fp32 GEMM (FFMA2 inner loop): g_tmp[M,128] = A[M,K] @ B[K,128]
// A = (A_GH ? g_h : Aparam). BM=128, BN=128, BK=8; 256 threads; 8x8 microtile.
// Accumulators held as 32 packed f32x2 pairs; B pairs come straight from the
// float4 smem loads; A is broadcast-duplicated on the alu pipe.
// ---------------------------------------------------------------------------
template <int K, bool A_GH>
__global__ void __launch_bounds__(256)
k_gemm(const float* __restrict__ Aparam, const float* __restrict__ B, int M) {
    constexpr int BM = 128, BN = 128, BK = 8;
    __shared__ __align__(16) float As[BK][BM + 4];  // A transposed (m-major per k)
    __shared__ __align__(16) float Bs[BK][BN + 4];

    const float* __restrict__ A = A_GH ? (const float*)g_h : Aparam;

    const int tid = threadIdx.x;
    const int row0 = blockIdx.x * BM;
    const int tx = tid & 15;          // col group: cols tx*8 .. +7
    const int ty = tid >> 4;          // row group: rows ty*8 .. +7

    u64 accp[8][4];                   // [row][pair]: cols (2p, 2p+1) of tx*8..+7
#pragma unroll
    for (int i = 0; i < 8; i++)
#pragma unroll
        for (int p = 0; p < 4; p++) accp[i][p] = 0ULL;   // {0.0f, 0.0f}

    // A-tile: 128 rows x 8 k = 256 float4 (one per thread)
    const int a_row  = tid >> 1;            // 0..127
    const int a_col4 = (tid & 1) * 4;       // 0,4
    const int a_gr   = row0 + a_row;
    const bool a_ok  = (a_gr < M);
    const float* a_ptr = A + (size_t)a_gr * K + a_col4;
    // B-tile: 8 rows x 128 cols = 256 float4 (one per thread)
    const int b_row  = tid >> 5;            // 0..7
    const int b_col4 = (tid & 31) * 4;
    const float* b_ptr = B + (size_t)b_row * BN + b_col4;

    // Prologue: fetch tile 0 into registers
    float4 av = make_float4(0.f, 0.f, 0.f, 0.f);
    if (a_ok) av = *(const float4*)(a_ptr);
    float4 bv = *(const float4*)(b_ptr);

    for (int k0 = 0; k0 < K; k0 += BK) {
        // Commit prefetched tile to smem
        As[a_col4 + 0][a_row] = av.x;
        As[a_col4 + 1][a_row] = av.y;
        As[a_col4 + 2][a_row] = av.z;
        As[a_col4 + 3][a_row] = av.w;
        *(float4*)&Bs[b_row][b_col4] = bv;
        __syncthreads();

        // Prefetch next tile (overlaps with compute below)
        if (k0 + BK < K) {
            av = make_float4(0.f, 0.f, 0.f, 0.f);
            if (a_ok) av = *(const float4*)(a_ptr + k0 + BK);
            bv = *(const float4*)(b_ptr + (size_t)(k0 + BK) * BN);
        }

#pragma unroll
        for (int kk = 0; kk < BK; kk++) {
            float a[8];
            *(float4*)&a[0] = *(const float4*)&As[kk][ty * 8];
            *(float4*)&a[4] = *(const float4*)&As[kk][ty * 8 + 4];
            float4 b0 = *(const float4*)&Bs[kk][tx * 8];
            float4 b1 = *(const float4*)&Bs[kk][tx * 8 + 4];
            u64 bp[4];
            bp[0] = pack2(b0.x, b0.y);
            bp[1] = pack2(b0.z, b0.w);
            bp[2] = pack2(b1.x, b1.y);
            bp[3] = pack2(b1.z, b1.w);
#pragma unroll
            for (int i = 0; i < 8; i++) {
                u64 ad = dup2(a[i]);
#pragma unroll
                for (int p = 0; p < 4; p++) ffma2(accp[i][p], ad, bp[p]);
            }
        }
        __syncthreads();
    }

#pragma unroll
    for (int i = 0; i < 8; i++) {
        int gr = row0 + ty * 8 + i;
        if (gr < M) {
            float r[8];
#pragma unroll
            for (int p = 0; p < 4; p++) unpack2(accp[i][p], r[2 * p], r[2 * p + 1]);
            float* cp = g_tmp + (size_t)gr * BN + tx * 8;
            *(float4*)cp       = make_float4(r[0], r[1], r[2], r[3]);
            *(float4*)(cp + 4) = make_float4(r[4], r[5], r[6], r[7]);
        }
    }
}

// ---------------------------------------------------------------------------
// Gather-based SpMM over g_tmp, fused epilogue.
// One warp per destination node: 32 lanes x float4 = 128 features.
// LAYER1: writes relu(agg + bias) to g_h.  else: writes agg + bias to outp.
// ---------------------------------------------------------------------------
template <bool LAYER1>
__global__ void __launch_bounds__(256)
k_spmm(float* __restrict__ outp, const float* __restrict__ bias, int n) {
    const int node = (blockIdx.x * blockDim.x + threadIdx.x) >> 5;
    const int lane = threadIdx.x & 31;
    if (node >= n) return;

    const float* t = (const float*)g_tmp;
    float c = g_dinv[node];
    c *= c;
    float4 acc = ((const float4*)(t + (size_t)node * HID_DIM))[lane];
    acc.x *= c; acc.y *= c; acc.z *= c; acc.w *= c;

    const int beg = g_rowptr[node];
    const int end = g_rowptr[node + 1];
    int e = beg;
    // 4-way unroll: 4 independent random-row loads in flight (MLP=4)
    for (; e + 3 < end; e += 4) {
        int2 e0 = g_edge[e],     e1 = g_edge[e + 1];
        int2 e2 = g_edge[e + 2], e3 = g_edge[e + 3];
        float c0 = __int_as_float(e0.y), c1 = __int_as_float(e1.y);
        float c2 = __int_as_float(e2.y), c3 = __int_as_float(e3.y);
        float4 v0 = ((const float4*)(t + (size_t)e0.x * HID_DIM))[lane];
        float4 v1 = ((const float4*)(t + (size_t)e1.x * HID_DIM))[lane];
        float4 v2 = ((const float4*)(t + (size_t)e2.x * HID_DIM))[lane];
        float4 v3 = ((const float4*)(t + (size_t)e3.x * HID_DIM))[lane];
        acc.x += c0 * v0.x + c1 * v1.x + c2 * v2.x + c3 * v3.x;
        acc.y += c0 * v0.y + c1 * v1.y + c2 * v2.y + c3 * v3.y;
        acc.z += c0 * v0.z + c1 * v1.z + c2 * v2.z + c3 * v3.z;
        acc.w += c0 * v0.w + c1 * v1.w + c2 * v2.w + c3 * v3.w;
    }
    for (; e < end; e++) {
        int2 e0 = g_edge[e];
        float c0 = __int_as_float(e0.y);
        float4 v0 = ((const float4*)(t + (size_t)e0.x * HID_DIM))[lane];
        acc.x += c0 * v0.x; acc.y += c0 * v0.y;
        acc.z += c0 * v0.z; acc.w += c0 * v0.w;
    }

    float4 b = ((const float4*)bias)[lane];
    acc.x += b.x; acc.y += b.y; acc.z += b.z; acc.w += b.w;
    if (LAYER1) {
        acc.x = fmaxf(acc.x, 0.0f); acc.y = fmaxf(acc.y, 0.0f);
        acc.z = fmaxf(acc.z, 0.0f); acc.w = fmaxf(acc.w, 0.0f);
        ((float4*)((float*)g_h + (size_t)node * HID_DIM))[lane] = acc;
    } else {
        ((float4*)(outp + (size_t)node * HID_DIM))[lane] = acc;
    }
}

// ---------------------------------------------------------------------------
// kernel_launch — only harness-owned pointers cross the host/device boundary.
// ---------------------------------------------------------------------------
extern "C" void kernel_launch(void* const* d_in, const int* in_sizes, int n_in,
                              void* d_out, int out_size) {
    const float* x  = (const float*)d_in[0];
    const void*  ei = d_in[1];                 // int32 or int64 — detected on device
    const float* w  = (const float*)d_in[2];
    const float* W1 = (const float*)d_in[3];
    const float* b1 = (const float*)d_in[4];
    const float* W2 = (const float*)d_in[5];
    const float* b2 = (const float*)d_in[6];
    float*       out = (float*)d_out;

    const int n = in_sizes[0] / IN_DIM;   // 100000
    const int E = in_sizes[2];            // 1600000

    const int T = 256;
    const int nodeBlocks = (n + T - 1) / T;
    const int edgeBlocks = (E + T - 1) / T;
    const int spmmBlocks = (int)(((size_t)n * 32 + T - 1) / T);  // warp/node
    const int gemmBlocks = (n + 127) / 128;

    // --- dtype detection + normalization + CSR build ---
    k_detect<<<1, 1>>>((const int*)ei);
    k_init<<<nodeBlocks, T>>>(n);
    k_edge_pass<<<edgeBlocks, T>>>(ei, w, E, n);
    k_dinv<<<nodeBlocks, T>>>(n);
    k_scan<<<1, 1024>>>(n);
    k_fill<<<edgeBlocks, T>>>(ei, w, E, n);

    // --- layer 1: g_tmp = x @ W1 ; g_h = relu(Agg(g_tmp) + b1) ---
    k_gemm<IN_DIM, false><<<gemmBlocks, T>>>(x, W1, n);
    k_spmm<true><<<spmmBlocks, T>>>(nullptr, b1, n);

    // --- layer 2: g_tmp = g_h @ W2 ; out = Agg(g_tmp) + b2 ---
    k_gemm<HID_DIM, true><<<gemmBlocks, T>>>(nullptr, W2, n);
    k_spmm<false><<<spmmBlocks, T>>>(out, b2, n);
}

// round 14
// speedup vs baseline: 1.5777x; 1.5777x over previous
#include <cuda_runtime.h>
#include <stdint.h>

#define NN       100000
#define NEMAX    1600000
#define IN_DIM   256
#define HID_DIM  128

// Scratch (allocation-free rule: __device__ globals, referenced DIRECTLY from
// kernels — no cudaGetSymbolAddress, no symbol-derived kernel arguments).
__device__ int   g_is64;                           // 1 if edge_index is int64
__device__ float g_dinv[NN];                       // rsqrt(weighted degree)
__device__ float g_deg[NN];                        // weighted degree accumulator
__device__ int   g_cnt[NN];                        // incoming-edge histogram
__device__ int   g_rowptr[NN + 1];                 // CSR row pointers (by dst)
__device__ int   g_cursor[NN];                     // fill cursors
__device__ int2  g_edge[NEMAX];                    // CSR: {src, norm-as-bits}
__device__ float g_tmp[(size_t)NN * HID_DIM];      // GEMM output (pre-agg)
__device__ float g_h[(size_t)NN * HID_DIM];        // layer-1 activations

// ---------------------------------------------------------------------------
// Edge-index dtype detection + safe accessors
// ---------------------------------------------------------------------------
// int64 node indices (< 100000, non-negative) have zero high words. Checking
// 8 odd-position int32 words == 0 identifies int64 vs int32 (P_false ~ 1e-40).
__global__ void k_detect(const int* __restrict__ ei32) {
    int is64 = 1;
    for (int i = 0; i < 8; i++)
        if (ei32[2 * i + 1] != 0) { is64 = 0; break; }
    g_is64 = is64;
}

__device__ __forceinline__ int edge_ld(const void* ei, size_t idx, int is64, int n) {
    int v = is64 ? (int)((const long long*)ei)[idx]
                 : ((const int*)ei)[idx];
    // clamp: any surprise degrades to wrong-but-measurable, not a crash
    return min(max(v, 0), n - 1);
}

// ---------------------------------------------------------------------------
// Normalization + CSR build
// ---------------------------------------------------------------------------
__global__ void k_init(int n) {
    int i = blockIdx.x * blockDim.x + threadIdx.x;
    if (i < n) { g_deg[i] = 1.0f; g_cnt[i] = 0; }   // self-loop weight = 1
}

// One pass over edges: weighted degree (float atomic) + histogram (int atomic)
__global__ void k_edge_pass(const void* __restrict__ ei,
                            const float* __restrict__ w, int E, int n) {
    int e = blockIdx.x * blockDim.x + threadIdx.x;
    if (e < E) {
        int is64 = g_is64;
        int d = edge_ld(ei, (size_t)E + e, is64, n);  // dst row of [2,E]
        atomicAdd(&g_deg[d], w[e]);
        atomicAdd(&g_cnt[d], 1);
    }
}

__global__ void k_dinv(int n) {
    int i = blockIdx.x * blockDim.x + threadIdx.x;
    if (i < n) g_dinv[i] = rsqrtf(g_deg[i]);        // deg >= 1 (self-loop)
}

// Single-block exclusive scan of g_cnt -> g_rowptr AND g_cursor.
__global__ void __launch_bounds__(1024) k_scan(int n) {
    __shared__ int part[1024];
    const int tid = threadIdx.x;
    const int per = (n + 1023) >> 10;
    const int s0 = tid * per;
    const int s1 = min(s0 + per, n);
    int s = 0;
    for (int i = s0; i < s1; i++) s += g_cnt[i];
    part[tid] = s;
    __syncthreads();
    for (int off = 1; off < 1024; off <<= 1) {
        int add = (tid >= off) ? part[tid - off] : 0;
        __syncthreads();
        part[tid] += add;
        __syncthreads();
    }
    int base = (tid == 0) ? 0 : part[tid - 1];
    for (int i = s0; i < s1; i++) {
        g_rowptr[i] = base;
        g_cursor[i] = base;
        base += g_cnt[i];
    }
    if (tid == 1023) g_rowptr[n] = part[1023];
}

// Scatter edges into CSR slots; precompute norm = dinv[src]*w*dinv[dst].
__global__ void k_fill(const void* __restrict__ ei,
                       const float* __restrict__ w, int E, int n) {
    int e = blockIdx.x * blockDim.x + threadIdx.x;
    if (e < E) {
        int is64 = g_is64;
        int s = edge_ld(ei, (size_t)e, is64, n);
        int d = edge_ld(ei, (size_t)E + e, is64, n);
        int pos = atomicAdd(&g_cursor[d], 1);
        float nv = g_dinv[s] * w[e] * g_dinv[d];
        g_edge[pos] = make_int2(s, __float_as_int(nv));
    }
}

// ---------------------------------------------------------------------------
// Tiled fp32 GEMM: g_tmp[M,128] = A[M,K] @ B[K,128]
// A = (A_GH ? g_h : Aparam). BM=128, BN=128, BK=16; 256 threads; 8x8 microtile.
// Double-buffered smem, ONE __syncthreads() per K-stage; next stage prefetched
// into registers while current stage is consumed.
// ---------------------------------------------------------------------------
template <int K, bool A_GH>
__global__ void __launch_bounds__(256)
k_gemm(const float* __restrict__ Aparam, const float* __restrict__ B, int M) {
    constexpr int BM = 128, BN = 128, BK = 16;
    __shared__ __align__(16) float As[2][BK][BM + 4];  // A transposed per k
    __shared__ __align__(16) float Bs[2][BK][BN + 4];

    const float* __restrict__ A = A_GH ? (const float*)g_h : Aparam;

    const int tid = threadIdx.x;
    const int row0 = blockIdx.x * BM;
    const int tx = tid & 15;          // col group: cols tx*8 .. +7
    const int ty = tid >> 4;          // row group: rows ty*8 .. +7

    float acc[8][8];
#pragma unroll
    for (int i = 0; i < 8; i++)
#pragma unroll
        for (int j = 0; j < 8; j++) acc[i][j] = 0.0f;

    // A-tile: 128 rows x 16 k = 512 float4; thread handles f = tid, tid+256
    // f -> row = f>>2, col4 = (f&3)*4
    const int ar0 = tid >> 2,        ac0 = (tid & 3) * 4;
    const int ar1 = (tid + 256) >> 2, ac1 = (tid & 3) * 4;   // (f+256)&3 == f&3
    const int ag0 = row0 + ar0;
    const int ag1 = row0 + ar1;
    const bool aok0 = (ag0 < M);
    const bool aok1 = (ag1 < M);
    // B-tile: 16 rows x 128 cols = 512 float4; f -> row = f>>5, col4 = (f&31)*4
    const int br0 = tid >> 5,        bc0 = (tid & 31) * 4;
    const int br1 = (tid + 256) >> 5, bc1 = (tid & 31) * 4;

    const int S = K / BK;
    const float4 z4 = make_float4(0.f, 0.f, 0.f, 0.f);

    // Prologue: fetch stage 0
    float4 a0 = aok0 ? *(const float4*)(A + (size_t)ag0 * K + ac0) : z4;
    float4 a1 = aok1 ? *(const float4*)(A + (size_t)ag1 * K + ac1) : z4;
    float4 b0 = *(const float4*)(B + (size_t)br0 * BN + bc0);
    float4 b1 = *(const float4*)(B + (size_t)br1 * BN + bc1);

    // Commit stage 0 to buffer 0 (A transposed)
    As[0][ac0 + 0][ar0] = a0.x; As[0][ac0 + 1][ar0] = a0.y;
    As[0][ac0 + 2][ar0] = a0.z; As[0][ac0 + 3][ar0] = a0.w;
    As[0][ac1 + 0][ar1] = a1.x; As[0][ac1 + 1][ar1] = a1.y;
    As[0][ac1 + 2][ar1] = a1.z; As[0][ac1 + 3][ar1] = a1.w;
    *(float4*)&Bs[0][br0][bc0] = b0;
    *(float4*)&Bs[0][br1][bc1] = b1;

    for (int s = 0; s < S; s++) {
        __syncthreads();   // stage-s stores visible; stage-(s-1) reads done

        // Prefetch stage s+1 into registers (overlaps compute below)
        if (s + 1 < S) {
            const int k0 = (s + 1) * BK;
            a0 = aok0 ? *(const float4*)(A + (size_t)ag0 * K + k0 + ac0) : z4;
            a1 = aok1 ? *(const float4*)(A + (size_t)ag1 * K + k0 + ac1) : z4;
            b0 = *(const float4*)(B + (size_t)(k0 + br0) * BN + bc0);
            b1 = *(const float4*)(B + (size_t)(k0 + br1) * BN + bc1);
        }

        const int buf = s & 1;
#pragma unroll
        for (int kk = 0; kk < BK; kk++) {
            float a[8], b[8];
            *(float4*)&a[0] = *(const float4*)&As[buf][kk][ty * 8];
            *(float4*)&a[4] = *(const float4*)&As[buf][kk][ty * 8 + 4];
            *(float4*)&b[0] = *(const float4*)&Bs[buf][kk][tx * 8];
            *(float4*)&b[4] = *(const float4*)&Bs[buf][kk][tx * 8 + 4];
#pragma unroll
            for (int i = 0; i < 8; i++)
#pragma unroll
                for (int j = 0; j < 8; j++) acc[i][j] += a[i] * b[j];
        }

        // Commit prefetched stage to the other buffer (read by next iteration)
        if (s + 1 < S) {
            const int nb = buf ^ 1;
            As[nb][ac0 + 0][ar0] = a0.x; As[nb][ac0 + 1][ar0] = a0.y;
            As[nb][ac0 + 2][ar0] = a0.z; As[nb][ac0 + 3][ar0] = a0.w;
            As[nb][ac1 + 0][ar1] = a1.x; As[nb][ac1 + 1][ar1] = a1.y;
            As[nb][ac1 + 2][ar1] = a1.z; As[nb][ac1 + 3][ar1] = a1.w;
            *(float4*)&Bs[nb][br0][bc0] = b0;
            *(float4*)&Bs[nb][br1][bc1] = b1;
        }
    }

#pragma unroll
    for (int i = 0; i < 8; i++) {
        int gr = row0 + ty * 8 + i;
        if (gr < M) {
            float* cp = g_tmp + (size_t)gr * BN + tx * 8;
            *(float4*)cp       = make_float4(acc[i][0], acc[i][1], acc[i][2], acc[i][3]);
            *(float4*)(cp + 4) = make_float4(acc[i][4], acc[i][5], acc[i][6], acc[i][7]);
        }
    }
}

// ---------------------------------------------------------------------------
// Gather-based SpMM over g_tmp, fused epilogue.
// One warp per destination node: 32 lanes x float4 = 128 features.
// 8-wide edge unroll: 8 independent random-row loads in flight (MLP=8).
// LAYER1: writes relu(agg + bias) to g_h.  else: writes agg + bias to outp.
// ---------------------------------------------------------------------------
template <bool LAYER1>
__global__ void __launch_bounds__(256)
k_spmm(float* __restrict__ outp, const float* __restrict__ bias, int n) {
    const int node = (blockIdx.x * blockDim.x + threadIdx.x) >> 5;
    const int lane = threadIdx.x & 31;
    if (node >= n) return;

    const float* t = (const float*)g_tmp;
    float c = g_dinv[node];
    c *= c;
    float4 acc = ((const float4*)(t + (size_t)node * HID_DIM))[lane];
    acc.x *= c; acc.y *= c; acc.z *= c; acc.w *= c;

    const int beg = g_rowptr[node];
    const int end = g_rowptr[node + 1];
    int e = beg;
    for (; e + 7 < end; e += 8) {
        int2 ee[8];
#pragma unroll
        for (int q = 0; q < 8; q++) ee[q] = g_edge[e + q];
        float4 vv[8];
#pragma unroll
        for (int q = 0; q < 8; q++)
            vv[q] = ((const float4*)(t + (size_t)ee[q].x * HID_DIM))[lane];
#pragma unroll
        for (int q = 0; q < 8; q++) {
            float cq = __int_as_float(ee[q].y);
            acc.x += cq * vv[q].x; acc.y += cq * vv[q].y;
            acc.z += cq * vv[q].z; acc.w += cq * vv[q].w;
        }
    }
    for (; e + 3 < end; e += 4) {
        int2 e0 = g_edge[e],     e1 = g_edge[e + 1];
        int2 e2 = g_edge[e + 2], e3 = g_edge[e + 3];
        float c0 = __int_as_float(e0.y), c1 = __int_as_float(e1.y);
        float c2 = __int_as_float(e2.y), c3 = __int_as_float(e3.y);
        float4 v0 = ((const float4*)(t + (size_t)e0.x * HID_DIM))[lane];
        float4 v1 = ((const float4*)(t + (size_t)e1.x * HID_DIM))[lane];
        float4 v2 = ((const float4*)(t + (size_t)e2.x * HID_DIM))[lane];
        float4 v3 = ((const float4*)(t + (size_t)e3.x * HID_DIM))[lane];
        acc.x += c0 * v0.x + c1 * v1.x + c2 * v2.x + c3 * v3.x;
        acc.y += c0 * v0.y + c1 * v1.y + c2 * v2.y + c3 * v3.y;
        acc.z += c0 * v0.z + c1 * v1.z + c2 * v2.z + c3 * v3.z;
        acc.w += c0 * v0.w + c1 * v1.w + c2 * v2.w + c3 * v3.w;
    }
    for (; e < end; e++) {
        int2 e0 = g_edge[e];
        float c0 = __int_as_float(e0.y);
        float4 v0 = ((const float4*)(t + (size_t)e0.x * HID_DIM))[lane];
        acc.x += c0 * v0.x; acc.y += c0 * v0.y;
        acc.z += c0 * v0.z; acc.w += c0 * v0.w;
    }

    float4 b = ((const float4*)bias)[lane];
    acc.x += b.x; acc.y += b.y; acc.z += b.z; acc.w += b.w;
    if (LAYER1) {
        acc.x = fmaxf(acc.x, 0.0f); acc.y = fmaxf(acc.y, 0.0f);
        acc.z = fmaxf(acc.z, 0.0f); acc.w = fmaxf(acc.w, 0.0f);
        ((float4*)((float*)g_h + (size_t)node * HID_DIM))[lane] = acc;
    } else {
        ((float4*)(outp + (size_t)node * HID_DIM))[lane] = acc;
    }
}

// ---------------------------------------------------------------------------
// kernel_launch — only harness-owned pointers cross the host/device boundary.
// ---------------------------------------------------------------------------
extern "C" void kernel_launch(void* const* d_in, const int* in_sizes, int n_in,
                              void* d_out, int out_size) {
    const float* x  = (const float*)d_in[0];
    const void*  ei = d_in[1];                 // int32 or int64 — detected on device
    const float* w  = (const float*)d_in[2];
    const float* W1 = (const float*)d_in[3];
    const float* b1 = (const float*)d_in[4];
    const float* W2 = (const float*)d_in[5];
    const float* b2 = (const float*)d_in[6];
    float*       out = (float*)d_out;

    const int n = in_sizes[0] / IN_DIM;   // 100000
    const int E = in_sizes[2];            // 1600000

    const int T = 256;
    const int nodeBlocks = (n + T - 1) / T;
    const int edgeBlocks = (E + T - 1) / T;
    const int spmmBlocks = (int)(((size_t)n * 32 + T - 1) / T);  // warp/node
    const int gemmBlocks = (n + 127) / 128;

    // --- dtype detection + normalization + CSR build ---
    k_detect<<<1, 1>>>((const int*)ei);
    k_init<<<nodeBlocks, T>>>(n);
    k_edge_pass<<<edgeBlocks, T>>>(ei, w, E, n);
    k_dinv<<<nodeBlocks, T>>>(n);
    k_scan<<<1, 1024>>>(n);
    k_fill<<<edgeBlocks, T>>>(ei, w, E, n);

    // --- layer 1: g_tmp = x @ W1 ; g_h = relu(Agg(g_tmp) + b1) ---
    k_gemm<IN_DIM, false><<<gemmBlocks, T>>>(x, W1, n);
    k_spmm<true><<<spmmBlocks, T>>>(nullptr, b1, n);

    // --- layer 2: g_tmp = g_h @ W2 ; out = Agg(g_tmp) + b2 ---
    k_gemm<HID_DIM, true><<<gemmBlocks, T>>>(nullptr, W2, n);
    k_spmm<false><<<spmmBlocks, T>>>(out, b2, n);
}

// round 17
// speedup vs baseline: 1.8943x; 1.2007x over previous
#include <cuda_runtime.h>
#include <cuda_bf16.h>
#include <stdint.h>

#define NN       100000
#define NEMAX    1600000
#define IN_DIM   256
#define HID_DIM  128

// Scratch (allocation-free rule: __device__ globals, referenced DIRECTLY).
__device__ int   g_is64;
__device__ float g_dinv[NN];
__device__ float g_deg[NN];
__device__ int   g_cnt[NN];
__device__ int   g_rowptr[NN + 1];
__device__ int   g_cursor[NN];
__device__ int2  g_edge[NEMAX];
__device__ float g_tmp[(size_t)NN * HID_DIM];      // GEMM output (fp32)
// split-bf16 operands (x = hi + lo, each bf16)
__device__ __nv_bfloat16 g_xh[(size_t)NN * IN_DIM],  g_xl[(size_t)NN * IN_DIM];
__device__ __nv_bfloat16 g_hh[(size_t)NN * HID_DIM], g_hl[(size_t)NN * HID_DIM];
__device__ __nv_bfloat16 g_w1h[IN_DIM * HID_DIM],  g_w1l[IN_DIM * HID_DIM];
__device__ __nv_bfloat16 g_w2h[HID_DIM * HID_DIM], g_w2l[HID_DIM * HID_DIM];

// ---------------------------------------------------------------------------
// fp32 -> split-bf16 conversion (hi = bf16(v), lo = bf16(v - hi))
// ---------------------------------------------------------------------------
__device__ __forceinline__ uint32_t pack_bf2(float a, float b) {
    __nv_bfloat16 ha = __float2bfloat16(a), hb = __float2bfloat16(b);
    return (uint32_t)__bfloat16_as_ushort(ha) |
           ((uint32_t)__bfloat16_as_ushort(hb) << 16);
}
__device__ __forceinline__ float bf_res(float v) {
    return v - __bfloat162float(__float2bfloat16(v));
}

template <int DST>
__global__ void k_cvt(const float* __restrict__ src, int nElem4) {
    int i = blockIdx.x * blockDim.x + threadIdx.x;
    if (i >= nElem4) return;
    float4 v = ((const float4*)src)[i];
    uint2 hv, lv;
    hv.x = pack_bf2(v.x, v.y);               hv.y = pack_bf2(v.z, v.w);
    lv.x = pack_bf2(bf_res(v.x), bf_res(v.y)); lv.y = pack_bf2(bf_res(v.z), bf_res(v.w));
    __nv_bfloat16* hp = DST == 0 ? g_xh : DST == 1 ? g_w1h : g_w2h;
    __nv_bfloat16* lp = DST == 0 ? g_xl : DST == 1 ? g_w1l : g_w2l;
    *(uint2*)(hp + (size_t)i * 4) = hv;
    *(uint2*)(lp + (size_t)i * 4) = lv;
}

// ---------------------------------------------------------------------------
// Edge-index dtype detection + safe accessors
// ---------------------------------------------------------------------------
__global__ void k_detect(const int* __restrict__ ei32) {
    int is64 = 1;
    for (int i = 0; i < 8; i++)
        if (ei32[2 * i + 1] != 0) { is64 = 0; break; }
    g_is64 = is64;
}

__device__ __forceinline__ int edge_ld(const void* ei, size_t idx, int is64, int n) {
    int v = is64 ? (int)((const long long*)ei)[idx] : ((const int*)ei)[idx];
    return min(max(v, 0), n - 1);
}

// ---------------------------------------------------------------------------
// Normalization + CSR build
// ---------------------------------------------------------------------------
__global__ void k_init(int n) {
    int i = blockIdx.x * blockDim.x + threadIdx.x;
    if (i < n) { g_deg[i] = 1.0f; g_cnt[i] = 0; }
}

__global__ void k_edge_pass(const void* __restrict__ ei,
                            const float* __restrict__ w, int E, int n) {
    int e = blockIdx.x * blockDim.x + threadIdx.x;
    if (e < E) {
        int is64 = g_is64;
        int d = edge_ld(ei, (size_t)E + e, is64, n);
        atomicAdd(&g_deg[d], w[e]);
        atomicAdd(&g_cnt[d], 1);
    }
}

__global__ void k_dinv(int n) {
    int i = blockIdx.x * blockDim.x + threadIdx.x;
    if (i < n) g_dinv[i] = rsqrtf(g_deg[i]);
}

__global__ void __launch_bounds__(1024) k_scan(int n) {
    __shared__ int part[1024];
    const int tid = threadIdx.x;
    const int per = (n + 1023) >> 10;
    const int s0 = tid * per;
    const int s1 = min(s0 + per, n);
    int s = 0;
    for (int i = s0; i < s1; i++) s += g_cnt[i];
    part[tid] = s;
    __syncthreads();
    for (int off = 1; off < 1024; off <<= 1) {
        int add = (tid >= off) ? part[tid - off] : 0;
        __syncthreads();
        part[tid] += add;
        __syncthreads();
    }
    int base = (tid == 0) ? 0 : part[tid - 1];
    for (int i = s0; i < s1; i++) {
        g_rowptr[i] = base;
        g_cursor[i] = base;
        base += g_cnt[i];
    }
    if (tid == 1023) g_rowptr[n] = part[1023];
}

__global__ void k_fill(const void* __restrict__ ei,
                       const float* __restrict__ w, int E, int n) {
    int e = blockIdx.x * blockDim.x + threadIdx.x;
    if (e < E) {
        int is64 = g_is64;
        int s = edge_ld(ei, (size_t)e, is64, n);
        int d = edge_ld(ei, (size_t)E + e, is64, n);
        int pos = atomicAdd(&g_cursor[d], 1);
        float nv = g_dinv[s] * w[e] * g_dinv[d];
        g_edge[pos] = make_int2(s, __float_as_int(nv));
    }
}

// ---------------------------------------------------------------------------
// mma.sync / ldmatrix helpers
// ---------------------------------------------------------------------------
__device__ __forceinline__ void ldsm4(uint32_t addr, uint32_t* r) {
    asm volatile("ldmatrix.sync.aligned.m8n8.x4.shared.b16 {%0,%1,%2,%3}, [%4];"
                 : "=r"(r[0]), "=r"(r[1]), "=r"(r[2]), "=r"(r[3]) : "r"(addr));
}
__device__ __forceinline__ void ldsm4t(uint32_t addr, uint32_t* r) {
    asm volatile("ldmatrix.sync.aligned.m8n8.x4.trans.shared.b16 {%0,%1,%2,%3}, [%4];"
                 : "=r"(r[0]), "=r"(r[1]), "=r"(r[2]), "=r"(r[3]) : "r"(addr));
}
__device__ __forceinline__ void mma_bf16(float* c, const uint32_t* a, const uint32_t* b) {
    asm volatile("mma.sync.aligned.m16n8k16.row.col.f32.bf16.bf16.f32 "
                 "{%0,%1,%2,%3},{%4,%5,%6,%7},{%8,%9},{%0,%1,%2,%3};"
                 : "+f"(c[0]), "+f"(c[1]), "+f"(c[2]), "+f"(c[3])
                 : "r"(a[0]), "r"(a[1]), "r"(a[2]), "r"(a[3]), "r"(b[0]), "r"(b[1]));
}

// ---------------------------------------------------------------------------
// Split-bf16 tensor-core GEMM: g_tmp[M,128] = A @ B,
// A = Ah+Al [M,K], B = Bh+Bl [K,128]; acc += Ah*Bh + Ah*Bl + Al*Bh (fp32).
// BM=128, BN=128, BK=16; 256 threads = 8 warps (2n x 4m), warp tile 32x64.
// Double-buffered smem, 1 barrier/stage. A smem [m][k] pitch 24 halves (48B,
// conflict-free ldmatrix); B smem [k][n] pitch 136 halves (272B, conflict-free
// ldmatrix.trans).
// ---------------------------------------------------------------------------
template <int K, bool L2>
__global__ void __launch_bounds__(256)
k_gemm_mma(int M) {
    constexpr int BM = 128, BN = 128;
    constexpr int AP = 24;    // A smem row pitch (halves)
    constexpr int BP = 136;   // B smem row pitch (halves)
    __shared__ __align__(16) __nv_bfloat16 As[2][2][BM * AP];  // [buf][part]
    __shared__ __align__(16) __nv_bfloat16 Bs[2][2][16 * BP];

    const __nv_bfloat16* __restrict__ Ah = L2 ? g_hh : g_xh;
    const __nv_bfloat16* __restrict__ Al = L2 ? g_hl : g_xl;
    const __nv_bfloat16* __restrict__ Bh = L2 ? g_w2h : g_w1h;
    const __nv_bfloat16* __restrict__ Bl = L2 ? g_w2l : g_w1l;

    const int tid = threadIdx.x, lane = tid & 31, wid = tid >> 5;
    const int row0 = blockIdx.x * BM;
    const int wm = (wid >> 1) * 32;   // warp m-offset (0..96)
    const int wn = (wid & 1) * 64;    // warp n-offset (0/64)

    // gmem load mapping: A: 128 rows x 16 halves, 8 halves (16B) per thread
    const int a_row = tid >> 1, a_seg = (tid & 1) * 8;
    const int ag = row0 + a_row;
    const bool aok = (ag < M);
    // B: 16 rows x 128 halves
    const int b_row = tid >> 4, b_seg = (tid & 15) * 8;

    float acc[2][8][4];
#pragma unroll
    for (int mt = 0; mt < 2; mt++)
#pragma unroll
        for (int nt = 0; nt < 8; nt++)
#pragma unroll
            for (int q = 0; q < 4; q++) acc[mt][nt][q] = 0.0f;

    const int S = K / 16;
    const uint4 z = make_uint4(0, 0, 0, 0);
    uint4 pa0, pa1, pb0, pb1;

    // Prologue: fetch + commit stage 0
    pa0 = aok ? *(const uint4*)(Ah + (size_t)ag * K + a_seg) : z;
    pa1 = aok ? *(const uint4*)(Al + (size_t)ag * K + a_seg) : z;
    pb0 = *(const uint4*)(Bh + (size_t)b_row * BN + b_seg);
    pb1 = *(const uint4*)(Bl + (size_t)b_row * BN + b_seg);
    *(uint4*)&As[0][0][a_row * AP + a_seg] = pa0;
    *(uint4*)&As[0][1][a_row * AP + a_seg] = pa1;
    *(uint4*)&Bs[0][0][b_row * BP + b_seg] = pb0;
    *(uint4*)&Bs[0][1][b_row * BP + b_seg] = pb1;

    // ldmatrix per-thread half-offsets
    const int a_off = (wm + (lane & 15)) * AP + (lane >> 4) * 8;      // + mt*16*AP
    const int b_off = (lane & 15) * BP + wn + (lane >> 4) * 8;        // + nt2*16

    for (int s = 0; s < S; s++) {
        __syncthreads();

        if (s + 1 < S) {
            const int k0 = (s + 1) * 16;
            pa0 = aok ? *(const uint4*)(Ah + (size_t)ag * K + k0 + a_seg) : z;
            pa1 = aok ? *(const uint4*)(Al + (size_t)ag * K + k0 + a_seg) : z;
            pb0 = *(const uint4*)(Bh + (size_t)(k0 + b_row) * BN + b_seg);
            pb1 = *(const uint4*)(Bl + (size_t)(k0 + b_row) * BN + b_seg);
        }

        const int buf = s & 1;
        uint32_t ah[2][4], al[2][4], bh[4][4], bl[4][4];
#pragma unroll
        for (int mt = 0; mt < 2; mt++) {
            uint32_t adh = (uint32_t)__cvta_generic_to_shared(&As[buf][0][a_off + mt * 16 * AP]);
            uint32_t adl = (uint32_t)__cvta_generic_to_shared(&As[buf][1][a_off + mt * 16 * AP]);
            ldsm4(adh, ah[mt]);
            ldsm4(adl, al[mt]);
        }
#pragma unroll
        for (int nt2 = 0; nt2 < 4; nt2++) {
            uint32_t bdh = (uint32_t)__cvta_generic_to_shared(&Bs[buf][0][b_off + nt2 * 16]);
            uint32_t bdl = (uint32_t)__cvta_generic_to_shared(&Bs[buf][1][b_off + nt2 * 16]);
            ldsm4t(bdh, bh[nt2]);
            ldsm4t(bdl, bl[nt2]);
        }
#pragma unroll
        for (int mt = 0; mt < 2; mt++)
#pragma unroll
            for (int nt = 0; nt < 8; nt++) {
                const uint32_t* bph = &bh[nt >> 1][(nt & 1) * 2];
                const uint32_t* bpl = &bl[nt >> 1][(nt & 1) * 2];
                mma_bf16(acc[mt][nt], ah[mt], bph);   // Ah*Bh
                mma_bf16(acc[mt][nt], ah[mt], bpl);   // Ah*Bl
                mma_bf16(acc[mt][nt], al[mt], bph);   // Al*Bh
            }

        if (s + 1 < S) {
            const int nb = buf ^ 1;
            *(uint4*)&As[nb][0][a_row * AP + a_seg] = pa0;
            *(uint4*)&As[nb][1][a_row * AP + a_seg] = pa1;
            *(uint4*)&Bs[nb][0][b_row * BP + b_seg] = pb0;
            *(uint4*)&Bs[nb][1][b_row * BP + b_seg] = pb1;
        }
    }

    // Epilogue: C fragment (m16n8): c0,c1 @ (row=lane>>2, col=(lane&3)*2), c2,c3 @ row+8
#pragma unroll
    for (int mt = 0; mt < 2; mt++) {
        int r = row0 + wm + mt * 16 + (lane >> 2);
#pragma unroll
        for (int nt = 0; nt < 8; nt++) {
            int c = wn + nt * 8 + (lane & 3) * 2;
            if (r < M)
                *(float2*)(g_tmp + (size_t)r * BN + c) =
                    make_float2(acc[mt][nt][0], acc[mt][nt][1]);
            if (r + 8 < M)
                *(float2*)(g_tmp + (size_t)(r + 8) * BN + c) =
                    make_float2(acc[mt][nt][2], acc[mt][nt][3]);
        }
    }
}

// ---------------------------------------------------------------------------
// Gather-based SpMM over g_tmp, fused epilogue.
// LAYER1: writes relu(agg+bias) as split-bf16 to g_hh/g_hl.
// else:   writes agg+bias fp32 to outp.
// ---------------------------------------------------------------------------
template <bool LAYER1>
__global__ void __launch_bounds__(256)
k_spmm(float* __restrict__ outp, const float* __restrict__ bias, int n) {
    const int node = (blockIdx.x * blockDim.x + threadIdx.x) >> 5;
    const int lane = threadIdx.x & 31;
    if (node >= n) return;

    const float* t = (const float*)g_tmp;
    float c = g_dinv[node];
    c *= c;
    float4 acc = ((const float4*)(t + (size_t)node * HID_DIM))[lane];
    acc.x *= c; acc.y *= c; acc.z *= c; acc.w *= c;

    const int beg = g_rowptr[node];
    const int end = g_rowptr[node + 1];
    int e = beg;
    for (; e + 7 < end; e += 8) {
        int2 ee[8];
#pragma unroll
        for (int q = 0; q < 8; q++) ee[q] = g_edge[e + q];
        float4 vv[8];
#pragma unroll
        for (int q = 0; q < 8; q++)
            vv[q] = ((const float4*)(t + (size_t)ee[q].x * HID_DIM))[lane];
#pragma unroll
        for (int q = 0; q < 8; q++) {
            float cq = __int_as_float(ee[q].y);
            acc.x += cq * vv[q].x; acc.y += cq * vv[q].y;
            acc.z += cq * vv[q].z; acc.w += cq * vv[q].w;
        }
    }
    for (; e + 3 < end; e += 4) {
        int2 e0 = g_edge[e],     e1 = g_edge[e + 1];
        int2 e2 = g_edge[e + 2], e3 = g_edge[e + 3];
        float c0 = __int_as_float(e0.y), c1 = __int_as_float(e1.y);
        float c2 = __int_as_float(e2.y), c3 = __int_as_float(e3.y);
        float4 v0 = ((const float4*)(t + (size_t)e0.x * HID_DIM))[lane];
        float4 v1 = ((const float4*)(t + (size_t)e1.x * HID_DIM))[lane];
        float4 v2 = ((const float4*)(t + (size_t)e2.x * HID_DIM))[lane];
        float4 v3 = ((const float4*)(t + (size_t)e3.x * HID_DIM))[lane];
        acc.x += c0 * v0.x + c1 * v1.x + c2 * v2.x + c3 * v3.x;
        acc.y += c0 * v0.y + c1 * v1.y + c2 * v2.y + c3 * v3.y;
        acc.z += c0 * v0.z + c1 * v1.z + c2 * v2.z + c3 * v3.z;
        acc.w += c0 * v0.w + c1 * v1.w + c2 * v2.w + c3 * v3.w;
    }
    for (; e < end; e++) {
        int2 e0 = g_edge[e];
        float c0 = __int_as_float(e0.y);
        float4 v0 = ((const float4*)(t + (size_t)e0.x * HID_DIM))[lane];
        acc.x += c0 * v0.x; acc.y += c0 * v0.y;
        acc.z += c0 * v0.z; acc.w += c0 * v0.w;
    }

    float4 b = ((const float4*)bias)[lane];
    acc.x += b.x; acc.y += b.y; acc.z += b.z; acc.w += b.w;
    if (LAYER1) {
        acc.x = fmaxf(acc.x, 0.0f); acc.y = fmaxf(acc.y, 0.0f);
        acc.z = fmaxf(acc.z, 0.0f); acc.w = fmaxf(acc.w, 0.0f);
        uint2 hv, lv;
        hv.x = pack_bf2(acc.x, acc.y);             hv.y = pack_bf2(acc.z, acc.w);
        lv.x = pack_bf2(bf_res(acc.x), bf_res(acc.y));
        lv.y = pack_bf2(bf_res(acc.z), bf_res(acc.w));
        size_t off = (size_t)node * HID_DIM + lane * 4;
        *(uint2*)(g_hh + off) = hv;
        *(uint2*)(g_hl + off) = lv;
    } else {
        ((float4*)(outp + (size_t)node * HID_DIM))[lane] = acc;
    }
}

// ---------------------------------------------------------------------------
// kernel_launch
// ---------------------------------------------------------------------------
extern "C" void kernel_launch(void* const* d_in, const int* in_sizes, int n_in,
                              void* d_out, int out_size) {
    const float* x  = (const float*)d_in[0];
    const void*  ei = d_in[1];
    const float* w  = (const float*)d_in[2];
    const float* W1 = (const float*)d_in[3];
    const float* b1 = (const float*)d_in[4];
    const float* W2 = (const float*)d_in[5];
    const float* b2 = (const float*)d_in[6];
    float*       out = (float*)d_out;

    const int n = in_sizes[0] / IN_DIM;   // 100000
    const int E = in_sizes[2];            // 1600000

    const int T = 256;
    const int nodeBlocks = (n + T - 1) / T;
    const int edgeBlocks = (E + T - 1) / T;
    const int spmmBlocks = (int)(((size_t)n * 32 + T - 1) / T);
    const int gemmBlocks = (n + 127) / 128;
    const int xq  = n * IN_DIM / 4;
    const int w1q = IN_DIM * HID_DIM / 4;
    const int w2q = HID_DIM * HID_DIM / 4;

    // --- split-bf16 conversions (independent of CSR chain) ---
    k_cvt<0><<<(xq + T - 1) / T, T>>>(x, xq);
    k_cvt<1><<<(w1q + T - 1) / T, T>>>(W1, w1q);
    k_cvt<2><<<(w2q + T - 1) / T, T>>>(W2, w2q);

    // --- dtype detection + normalization + CSR build ---
    k_detect<<<1, 1>>>((const int*)ei);
    k_init<<<nodeBlocks, T>>>(n);
    k_edge_pass<<<edgeBlocks, T>>>(ei, w, E, n);
    k_dinv<<<nodeBlocks, T>>>(n);
    k_scan<<<1, 1024>>>(n);
    k_fill<<<edgeBlocks, T>>>(ei, w, E, n);

    // --- layer 1: g_tmp = x @ W1 ; g_hh/g_hl = split(relu(Agg(g_tmp)+b1)) ---
    k_gemm_mma<IN_DIM, false><<<gemmBlocks, T>>>(n);
    k_spmm<true><<<spmmBlocks, T>>>(nullptr, b1, n);

    // --- layer 2: g_tmp = h @ W2 ; out = Agg(g_tmp) + b2 ---
    k_gemm_mma<HID_DIM, true><<<gemmBlocks, T>>>(n);
    k_spmm<false><<<spmmBlocks, T>>>(out, b2, n);
}